// round 3
// baseline (speedup 1.0000x reference)
#include <cuda_runtime.h>
#include <math.h>
#include <stdint.h>

// Problem shape (fixed for this problem instance)
#define BB 2
#define NN 4096
#define LL 512
#define CC 2048
#define HH 16
#define DD 128
#define MTOK (BB*NN)      // 8192 tokens (B*N)
#define MKV  (BB*LL)      // 1024 kv rows (B*L)
#define KI   (CC/4)       // 512 packed int8x4 per row

// -------------------- scratch (static device globals; no allocation) -----
__device__ int8_t g_qwq[(size_t)CC*CC];
__device__ float  g_swq[CC];
__device__ int8_t g_qwo[(size_t)CC*CC];
__device__ float  g_swo[CC];
__device__ int8_t g_qx[(size_t)MTOK*CC];
__device__ float  g_sx[MTOK];
__device__ float  g_q[(size_t)MTOK*CC];    // Q projection output [B*N][C]
__device__ float  g_k[(size_t)MKV*CC];     // K projection output [B*L][C]
__device__ float  g_v[(size_t)MKV*CC];     // V projection output [B*L][C]
__device__ float  g_o[(size_t)MTOK*CC];    // attention output    [B*N][C]
__device__ int8_t g_qo[(size_t)MTOK*CC];
__device__ float  g_so[MTOK];

// -------------------- per-row symmetric int8 quantization ----------------
// matches: s = max(max|x|/127, 1e-8); q = clip(round(x/s), -127, 127)
// rintf = round-half-to-even, identical to jnp.round. True division matches
// the reference's x/s rounding behavior at half-way points.
__global__ void quant_rows(const float* __restrict__ src,
                           int8_t* __restrict__ qdst,
                           float* __restrict__ sdst, int K) {
    int row = blockIdx.x;
    const float* p = src + (size_t)row * K;
    float m = 0.f;
    for (int i = threadIdx.x; i < K; i += blockDim.x) m = fmaxf(m, fabsf(p[i]));
    __shared__ float red[256];
    red[threadIdx.x] = m;
    __syncthreads();
    for (int s = 128; s > 0; s >>= 1) {
        if (threadIdx.x < s) red[threadIdx.x] = fmaxf(red[threadIdx.x], red[threadIdx.x + s]);
        __syncthreads();
    }
    float sc = fmaxf(red[0] / 127.0f, 1e-8f);
    int8_t* q = qdst + (size_t)row * K;
    for (int i = threadIdx.x; i < K; i += blockDim.x) {
        float r = rintf(p[i] / sc);
        r = fminf(fmaxf(r, -127.f), 127.f);
        q[i] = (int8_t)r;
    }
    if (threadIdx.x == 0) sdst[row] = sc;
}

// -------------------- int8 W8A8 GEMM (dp4a) -------------------------------
// C[m][n] = float( sum_k qa[m][k]*qb[n][k] ) * (sa[m]*sb[n]) + bias[n]
// Tiles: BM=128, BN=128, BK=64 bytes (16 ints). 256 threads, 8x8 per thread.
__global__ __launch_bounds__(256) void gemm_w8a8(
    const int8_t* __restrict__ qa, const int8_t* __restrict__ qb,
    const float* __restrict__ sa, const float* __restrict__ sb,
    const float* __restrict__ bias, float* __restrict__ out)
{
    __shared__ int As[128][17];
    __shared__ int Bs[128][17];
    const int* A = (const int*)qa;
    const int* Bm = (const int*)qb;
    int tid = threadIdx.x;
    int ty = tid >> 4, tx = tid & 15;
    int m0 = blockIdx.y * 128, n0 = blockIdx.x * 128;

    int acc[8][8];
#pragma unroll
    for (int i = 0; i < 8; i++)
#pragma unroll
        for (int j = 0; j < 8; j++) acc[i][j] = 0;

    for (int ks = 0; ks < KI; ks += 16) {
#pragma unroll
        for (int t = 0; t < 8; t++) {
            int idx = tid + t * 256;
            int r = idx >> 4, c = idx & 15;
            As[r][c] = A[(size_t)(m0 + r) * KI + ks + c];
            Bs[r][c] = Bm[(size_t)(n0 + r) * KI + ks + c];
        }
        __syncthreads();
#pragma unroll
        for (int kk = 0; kk < 16; kk++) {
            int a[8], b[8];
#pragma unroll
            for (int i = 0; i < 8; i++) a[i] = As[ty * 8 + i][kk];
#pragma unroll
            for (int j = 0; j < 8; j++) b[j] = Bs[tx + j * 16][kk];
#pragma unroll
            for (int i = 0; i < 8; i++)
#pragma unroll
                for (int j = 0; j < 8; j++)
                    acc[i][j] = __dp4a(a[i], b[j], acc[i][j]);
        }
        __syncthreads();
    }

#pragma unroll
    for (int i = 0; i < 8; i++) {
        int m = m0 + ty * 8 + i;
        float sam = sa[m];
#pragma unroll
        for (int j = 0; j < 8; j++) {
            int n = n0 + tx + j * 16;
            out[(size_t)m * CC + n] = (float)acc[i][j] * (sam * sb[n]) + bias[n];
        }
    }
}

// -------------------- fp32 GEMM for K/V projections -----------------------
// out[m][n] = sum_c cond[m][c]*W[n][c] + bias[n];  z=0 -> K, z=1 -> V
__global__ __launch_bounds__(256) void gemm_kv(
    const float* __restrict__ cond,
    const float* __restrict__ wk, const float* __restrict__ bk,
    const float* __restrict__ wv, const float* __restrict__ bv)
{
    __shared__ float As[128][17];
    __shared__ float Bs[128][17];
    const float* W    = blockIdx.z ? wv : wk;
    const float* bias = blockIdx.z ? bv : bk;
    float* out        = blockIdx.z ? g_v : g_k;

    int tid = threadIdx.x;
    int ty = tid >> 4, tx = tid & 15;
    int m0 = blockIdx.y * 128, n0 = blockIdx.x * 128;

    float acc[8][8];
#pragma unroll
    for (int i = 0; i < 8; i++)
#pragma unroll
        for (int j = 0; j < 8; j++) acc[i][j] = 0.f;

    for (int ks = 0; ks < CC; ks += 16) {
#pragma unroll
        for (int t = 0; t < 8; t++) {
            int idx = tid + t * 256;
            int r = idx >> 4, c = idx & 15;
            As[r][c] = cond[(size_t)(m0 + r) * CC + ks + c];
            Bs[r][c] = W[(size_t)(n0 + r) * CC + ks + c];
        }
        __syncthreads();
#pragma unroll
        for (int kk = 0; kk < 16; kk++) {
            float a[8], b[8];
#pragma unroll
            for (int i = 0; i < 8; i++) a[i] = As[ty * 8 + i][kk];
#pragma unroll
            for (int j = 0; j < 8; j++) b[j] = Bs[tx + j * 16][kk];
#pragma unroll
            for (int i = 0; i < 8; i++)
#pragma unroll
                for (int j = 0; j < 8; j++)
                    acc[i][j] = fmaf(a[i], b[j], acc[i][j]);
        }
        __syncthreads();
    }

#pragma unroll
    for (int i = 0; i < 8; i++) {
        int m = m0 + ty * 8 + i;
#pragma unroll
        for (int j = 0; j < 8; j++) {
            int n = n0 + tx + j * 16;
            out[(size_t)m * CC + n] = acc[i][j] + bias[n];
        }
    }
}

// -------------------- flash-style cross attention --------------------------
// grid (N/64, B*H), 256 threads (16x16). Q tile 64 rows, L chunks of 64.
// Thread (ty,tx): S frag rows ty*4..+3, cols tx+j*16; O frag rows ty*4..+3,
// cols tx+k*16 (conflict-free smem access patterns).
#define ATT_QK_STRIDE 129
#define ATT_S_STRIDE  65
#define ATT_SMEM ((3*64*ATT_QK_STRIDE + 64*ATT_S_STRIDE) * (int)sizeof(float))

__global__ __launch_bounds__(256) void attn_kernel(const float* __restrict__ mask)
{
    extern __shared__ float sm[];
    float* qs  = sm;                          // 64 x 129
    float* ks_ = qs  + 64 * ATT_QK_STRIDE;    // 64 x 129
    float* vs  = ks_ + 64 * ATT_QK_STRIDE;    // 64 x 129
    float* ss  = vs  + 64 * ATT_QK_STRIDE;    // 64 x 65

    int bh = blockIdx.y;
    int b = bh >> 4, h = bh & 15;
    int n0 = blockIdx.x * 64;
    int tid = threadIdx.x;
    int ty = tid >> 4, tx = tid & 15;
    const float inv_sqrt_d = 0.088388347648318447f;   // 1/sqrt(128)

    // load Q tile (pre-scaled)
    for (int idx = tid; idx < 64 * 128; idx += 256) {
        int r = idx >> 7, d = idx & 127;
        qs[r * ATT_QK_STRIDE + d] =
            g_q[((size_t)b * NN + n0 + r) * CC + h * DD + d] * inv_sqrt_d;
    }

    float m_i[4], l_i[4], oacc[4][8];
#pragma unroll
    for (int i = 0; i < 4; i++) {
        m_i[i] = -INFINITY;
        l_i[i] = 0.f;
#pragma unroll
        for (int k = 0; k < 8; k++) oacc[i][k] = 0.f;
    }

    for (int c0 = 0; c0 < LL; c0 += 64) {
        __syncthreads();   // previous chunk fully consumed (also covers Q tile on iter 0)
        for (int idx = tid; idx < 64 * 128; idx += 256) {
            int r = idx >> 7, d = idx & 127;
            size_t g = ((size_t)b * LL + c0 + r) * CC + h * DD + d;
            ks_[r * ATT_QK_STRIDE + d] = g_k[g];
            vs [r * ATT_QK_STRIDE + d] = g_v[g];
        }
        __syncthreads();

        // S = (Q * inv_sqrt_d) @ K^T
        float sacc[4][4];
#pragma unroll
        for (int i = 0; i < 4; i++)
#pragma unroll
            for (int j = 0; j < 4; j++) sacc[i][j] = 0.f;

#pragma unroll 8
        for (int d = 0; d < 128; d++) {
            float a[4], bb[4];
#pragma unroll
            for (int i = 0; i < 4; i++) a[i] = qs[(ty * 4 + i) * ATT_QK_STRIDE + d];
#pragma unroll
            for (int j = 0; j < 4; j++) bb[j] = ks_[(tx + j * 16) * ATT_QK_STRIDE + d];
#pragma unroll
            for (int i = 0; i < 4; i++)
#pragma unroll
                for (int j = 0; j < 4; j++) sacc[i][j] = fmaf(a[i], bb[j], sacc[i][j]);
        }

        // mask + online softmax (row reductions across the 16 tx lanes)
#pragma unroll
        for (int i = 0; i < 4; i++) {
            int row = n0 + ty * 4 + i;
            float rmax = -INFINITY;
#pragma unroll
            for (int j = 0; j < 4; j++) {
                sacc[i][j] += mask[((size_t)b * NN + row) * LL + c0 + tx + j * 16];
                rmax = fmaxf(rmax, sacc[i][j]);
            }
#pragma unroll
            for (int off = 1; off < 16; off <<= 1)
                rmax = fmaxf(rmax, __shfl_xor_sync(0xffffffffu, rmax, off));

            float nm = fmaxf(m_i[i], rmax);
            float corr = __expf(m_i[i] - nm);
            m_i[i] = nm;
            float ps = 0.f;
#pragma unroll
            for (int j = 0; j < 4; j++) {
                float p = __expf(sacc[i][j] - nm);
                sacc[i][j] = p;
                ps += p;
            }
#pragma unroll
            for (int off = 1; off < 16; off <<= 1)
                ps += __shfl_xor_sync(0xffffffffu, ps, off);
            l_i[i] = l_i[i] * corr + ps;
#pragma unroll
            for (int k = 0; k < 8; k++) oacc[i][k] *= corr;
        }

        // stage P into shared for the O GEMM
#pragma unroll
        for (int i = 0; i < 4; i++)
#pragma unroll
            for (int j = 0; j < 4; j++)
                ss[(ty * 4 + i) * ATT_S_STRIDE + tx + j * 16] = sacc[i][j];
        __syncthreads();

        // O += P @ V
#pragma unroll 4
        for (int jj = 0; jj < 64; jj++) {
            float p4[4], v8[8];
#pragma unroll
            for (int i = 0; i < 4; i++) p4[i] = ss[(ty * 4 + i) * ATT_S_STRIDE + jj];
#pragma unroll
            for (int k = 0; k < 8; k++) v8[k] = vs[jj * ATT_QK_STRIDE + tx + k * 16];
#pragma unroll
            for (int i = 0; i < 4; i++)
#pragma unroll
                for (int k = 0; k < 8; k++) oacc[i][k] = fmaf(p4[i], v8[k], oacc[i][k]);
        }
    }

#pragma unroll
    for (int i = 0; i < 4; i++) {
        float inv = 1.f / l_i[i];
        int row = n0 + ty * 4 + i;
#pragma unroll
        for (int k = 0; k < 8; k++)
            g_o[((size_t)b * NN + row) * CC + h * DD + tx + k * 16] = oacc[i][k] * inv;
    }
}

// -------------------- launcher --------------------------------------------
extern "C" void kernel_launch(void* const* d_in, const int* in_sizes, int n_in,
                              void* d_out, int out_size) {
    const float* x    = (const float*)d_in[0];
    const float* cond = (const float*)d_in[1];
    const float* mask = (const float*)d_in[2];
    const float* wq   = (const float*)d_in[3];
    const float* bq   = (const float*)d_in[4];
    const float* wk   = (const float*)d_in[5];
    const float* bk   = (const float*)d_in[6];
    const float* wv   = (const float*)d_in[7];
    const float* bv   = (const float*)d_in[8];
    const float* wo   = (const float*)d_in[9];
    const float* bo   = (const float*)d_in[10];
    float* out = (float*)d_out;

    void *p_qwq, *p_swq, *p_qwo, *p_swo, *p_qx, *p_sx, *p_q, *p_o, *p_qo, *p_so;
    cudaGetSymbolAddress(&p_qwq, g_qwq);
    cudaGetSymbolAddress(&p_swq, g_swq);
    cudaGetSymbolAddress(&p_qwo, g_qwo);
    cudaGetSymbolAddress(&p_swo, g_swo);
    cudaGetSymbolAddress(&p_qx,  g_qx);
    cudaGetSymbolAddress(&p_sx,  g_sx);
    cudaGetSymbolAddress(&p_q,   g_q);
    cudaGetSymbolAddress(&p_o,   g_o);
    cudaGetSymbolAddress(&p_qo,  g_qo);
    cudaGetSymbolAddress(&p_so,  g_so);

    // 1. quantize weights (wq, wo) and activations (x)
    quant_rows<<<CC, 256>>>(wq, (int8_t*)p_qwq, (float*)p_swq, CC);
    quant_rows<<<CC, 256>>>(wo, (int8_t*)p_qwo, (float*)p_swo, CC);
    quant_rows<<<MTOK, 256>>>(x, (int8_t*)p_qx, (float*)p_sx, CC);

    // 2. Q projection (W8A8)
    gemm_w8a8<<<dim3(CC / 128, MTOK / 128), 256>>>(
        (const int8_t*)p_qx, (const int8_t*)p_qwq,
        (const float*)p_sx, (const float*)p_swq, bq, (float*)p_q);

    // 3. K/V projections (fp32), fused across z
    gemm_kv<<<dim3(CC / 128, MKV / 128, 2), 256>>>(cond, wk, bk, wv, bv);

    // 4. attention
    cudaFuncSetAttribute(attn_kernel,
                         cudaFuncAttributeMaxDynamicSharedMemorySize, ATT_SMEM);
    attn_kernel<<<dim3(NN / 64, BB * HH), 256, ATT_SMEM>>>(mask);

    // 5. quantize attention output, O projection (W8A8) into d_out
    quant_rows<<<MTOK, 256>>>((const float*)p_o, (int8_t*)p_qo, (float*)p_so, CC);
    gemm_w8a8<<<dim3(CC / 128, MTOK / 128), 256>>>(
        (const int8_t*)p_qo, (const int8_t*)p_qwo,
        (const float*)p_so, (const float*)p_swo, bo, out);
}

// round 6
// speedup vs baseline: 1.3675x; 1.3675x over previous
#include <cuda_runtime.h>
#include <cuda_bf16.h>
#include <math.h>
#include <stdint.h>

// Problem shape (fixed for this problem instance)
#define BB 2
#define NN 4096
#define LL 512
#define CC 2048
#define HH 16
#define DD 128
#define MTOK (BB*NN)      // 8192 tokens (B*N)
#define MKV  (BB*LL)      // 1024 kv rows (B*L)

// -------------------- scratch (static device globals; no allocation) -----
__device__ __nv_bfloat16 g_qwq[(size_t)CC*CC];
__device__ float         g_swq[CC];
__device__ __nv_bfloat16 g_qwo[(size_t)CC*CC];
__device__ float         g_swo[CC];
__device__ __nv_bfloat16 g_qx[(size_t)MTOK*CC];
__device__ float         g_sx[MTOK];
__device__ float         g_q[(size_t)MTOK*CC];    // Q projection output [B*N][C]
__device__ float         g_k[(size_t)MKV*CC];     // K projection output [B*L][C]
__device__ float         g_v[(size_t)MKV*CC];     // V projection output [B*L][C]
__device__ float         g_o[(size_t)MTOK*CC];    // attention output    [B*N][C]
__device__ __nv_bfloat16 g_qo[(size_t)MTOK*CC];
__device__ float         g_so[MTOK];

// -------------------- small PTX helpers -----------------------------------
__device__ __forceinline__ uint32_t smem_u32(const void* p) {
    uint32_t a;
    asm("{ .reg .u64 t; cvta.to.shared.u64 t, %1; cvt.u32.u64 %0, t; }"
        : "=r"(a) : "l"(p));
    return a;
}

__device__ __forceinline__ void cp16(uint32_t dst, const void* src) {
    asm volatile("cp.async.cg.shared.global [%0], [%1], 16;" :: "r"(dst), "l"(src));
}

#define SW128(x) ((x) ^ (((x) >> 3) & 0x70))

#define LDSM4(r0, r1, r2, r3, addr) \
    asm volatile("ldmatrix.sync.aligned.m8n8.x4.shared.b16 {%0,%1,%2,%3}, [%4];" \
                 : "=r"(r0), "=r"(r1), "=r"(r2), "=r"(r3) : "r"(addr))

__device__ __forceinline__ void mma16816(float* d,
    uint32_t a0, uint32_t a1, uint32_t a2, uint32_t a3,
    uint32_t b0, uint32_t b1)
{
    asm volatile(
        "mma.sync.aligned.m16n8k16.row.col.f32.bf16.bf16.f32 "
        "{%0,%1,%2,%3}, {%4,%5,%6,%7}, {%8,%9}, {%0,%1,%2,%3};"
        : "+f"(d[0]), "+f"(d[1]), "+f"(d[2]), "+f"(d[3])
        : "r"(a0), "r"(a1), "r"(a2), "r"(a3), "r"(b0), "r"(b1));
}

// -------------------- per-row symmetric int8 quantization ----------------
// matches: s = max(max|x|/127, 1e-8); q = clip(round(x/s), -127, 127)
// Quantized values are integers in [-127,127] -> EXACT in bf16 (8-bit mantissa).
__global__ void quant_rows(const float* __restrict__ src,
                           __nv_bfloat16* __restrict__ qdst,
                           float* __restrict__ sdst, int K) {
    int row = blockIdx.x;
    const float* p = src + (size_t)row * K;
    float m = 0.f;
    for (int i = threadIdx.x; i < K; i += blockDim.x) m = fmaxf(m, fabsf(p[i]));
    __shared__ float red[256];
    red[threadIdx.x] = m;
    __syncthreads();
    for (int s = 128; s > 0; s >>= 1) {
        if (threadIdx.x < s) red[threadIdx.x] = fmaxf(red[threadIdx.x], red[threadIdx.x + s]);
        __syncthreads();
    }
    float sc = fmaxf(red[0] / 127.0f, 1e-8f);
    __nv_bfloat16* q = qdst + (size_t)row * K;
    for (int i = threadIdx.x; i < K; i += blockDim.x) {
        float r = rintf(p[i] / sc);
        r = fminf(fmaxf(r, -127.f), 127.f);
        q[i] = __float2bfloat16(r);     // exact (|r| <= 127 integer)
    }
    if (threadIdx.x == 0) sdst[row] = sc;
}

// -------------------- mma.sync bf16 GEMM (exact int32 W8A8) ----------------
// out[m][n] = float( sum_k qa[m][k]*qw[n][k] ) * (sa[m]*sw[n]) + bias[n]
// Both operands K-major bf16 holding exact integers in [-127,127].
// All partial sums < 2^25 -> fp32 accumulation is bit-exact int32.
// CTA tile 128x128, K-chunk 64 bf16 (128B rows, SW128 swizzle).
// 8 warps in 2(m) x 4(n) grid; warp tile 64x32 = 4x4 m16n8k16 fragments.
#define GNST 3
#define GSTAGE_BYTES 32768u             // A 16KB + B 16KB
#define GSM_A(s) ((unsigned)(s) * GSTAGE_BYTES)
#define GSM_B(s) (GSM_A(s) + 16384u)
#define GEMM_SMEM (GNST * GSTAGE_BYTES)
#define GNCH (CC / 64)                  // 32 K-chunks

__device__ __forceinline__ void gemm_load_stage(
    uint32_t smem_base, int s, int ks, int m0, int n0, int tid,
    const __nv_bfloat16* __restrict__ A, const __nv_bfloat16* __restrict__ W)
{
    size_t coff = (size_t)ks * 64;               // bf16 column offset
    uint32_t abase = smem_base + GSM_A(s);
    uint32_t bbase = smem_base + GSM_B(s);
#pragma unroll
    for (int j = 0; j < 4; j++) {                // A: 128 rows x 8 x 16B granules
        int g = tid + j * 256, r = g >> 3, i = g & 7;
        const char* src = (const char*)(A + (size_t)(m0 + r) * CC + coff) + i * 16;
        uint32_t off = (uint32_t)(r * 128 + i * 16);
        cp16(abase + SW128(off), src);
    }
#pragma unroll
    for (int j = 0; j < 4; j++) {                // B: 128 rows x 8 x 16B granules
        int g = tid + j * 256, r = g >> 3, i = g & 7;
        const char* src = (const char*)(W + (size_t)(n0 + r) * CC + coff) + i * 16;
        uint32_t off = (uint32_t)(r * 128 + i * 16);
        cp16(bbase + SW128(off), src);
    }
    asm volatile("cp.async.commit_group;" ::: "memory");
}

__global__ __launch_bounds__(256, 1) void gemm_tc(
    const __nv_bfloat16* __restrict__ A, const __nv_bfloat16* __restrict__ W,
    const float* __restrict__ sa, const float* __restrict__ sw,
    const float* __restrict__ bias, float* __restrict__ out)
{
    extern __shared__ char smem[];
    uint32_t sb = smem_u32(smem);
    int tid = threadIdx.x;
    int wid = tid >> 5, lid = tid & 31;
    int m0 = blockIdx.y * 128, n0 = blockIdx.x * 128;
    int wm = wid >> 2;        // 0..1 : 64-row slab
    int wn = wid & 3;         // 0..3 : 32-col slab

    // ldmatrix per-lane addressing: sub-matrix layout for m16x16 .x4 loads
    int sub = lid >> 3, le = lid & 7;
    int lrow = le + (sub & 1) * 8;       // row within 16-row tile
    int lcol = (sub >> 1) * 16;          // byte offset within 32B k16 step

    float acc[4][4][4];
#pragma unroll
    for (int mt = 0; mt < 4; mt++)
#pragma unroll
        for (int nt = 0; nt < 4; nt++)
#pragma unroll
            for (int q = 0; q < 4; q++) acc[mt][nt][q] = 0.f;

    // prologue: fill 3 stages
    gemm_load_stage(sb, 0, 0, m0, n0, tid, A, W);
    gemm_load_stage(sb, 1, 1, m0, n0, tid, A, W);
    gemm_load_stage(sb, 2, 2, m0, n0, tid, A, W);

    int a_row = wm * 64 + lrow;   // row in A tile for this lane
    int b_row = wn * 32 + lrow;   // row in B tile for this lane

    for (int ks = 0; ks < GNCH; ks++) {
        int s = ks % GNST;
        asm volatile("cp.async.wait_group %0;" :: "n"(GNST - 1) : "memory");
        __syncthreads();
        uint32_t abase = sb + GSM_A(s);
        uint32_t bbase = sb + GSM_B(s);

#pragma unroll
        for (int kt = 0; kt < 4; kt++) {           // 4 x k16 per 64-col chunk
            int kb = kt * 32 + lcol;
            uint32_t af[4][4];
#pragma unroll
            for (int mt = 0; mt < 4; mt++) {
                uint32_t addr = abase + SW128((uint32_t)((a_row + mt * 16) * 128 + kb));
                LDSM4(af[mt][0], af[mt][1], af[mt][2], af[mt][3], addr);
            }
            uint32_t bf[2][4];
#pragma unroll
            for (int np = 0; np < 2; np++) {
                uint32_t addr = bbase + SW128((uint32_t)((b_row + np * 16) * 128 + kb));
                LDSM4(bf[np][0], bf[np][1], bf[np][2], bf[np][3], addr);
            }
            // b fragment for n-tile (np*2)   = {r0, r2}; (np*2+1) = {r1, r3}
#pragma unroll
            for (int mt = 0; mt < 4; mt++) {
#pragma unroll
                for (int np = 0; np < 2; np++) {
                    mma16816(acc[mt][np * 2 + 0],
                             af[mt][0], af[mt][1], af[mt][2], af[mt][3],
                             bf[np][0], bf[np][2]);
                    mma16816(acc[mt][np * 2 + 1],
                             af[mt][0], af[mt][1], af[mt][2], af[mt][3],
                             bf[np][1], bf[np][3]);
                }
            }
        }
        __syncthreads();
        if (ks + GNST < GNCH)
            gemm_load_stage(sb, s, ks + GNST, m0, n0, tid, A, W);
    }

    // epilogue: c0,c1 -> (row=g, col=t*2,t*2+1); c2,c3 -> (row=g+8, same cols)
    int g = lid >> 2, t = lid & 3;
#pragma unroll
    for (int mt = 0; mt < 4; mt++) {
        int mA = m0 + wm * 64 + mt * 16 + g;
        int mB = mA + 8;
        float saA = sa[mA], saB = sa[mB];
        float* rowA = out + (size_t)mA * CC;
        float* rowB = out + (size_t)mB * CC;
#pragma unroll
        for (int nt = 0; nt < 4; nt++) {
            int n = n0 + wn * 32 + nt * 8 + t * 2;
            float2 vsw = *(const float2*)(sw + n);
            float2 vbi = *(const float2*)(bias + n);
            float2 oA, oB;
            oA.x = acc[mt][nt][0] * (saA * vsw.x) + vbi.x;
            oA.y = acc[mt][nt][1] * (saA * vsw.y) + vbi.y;
            oB.x = acc[mt][nt][2] * (saB * vsw.x) + vbi.x;
            oB.y = acc[mt][nt][3] * (saB * vsw.y) + vbi.y;
            *(float2*)(rowA + n) = oA;
            *(float2*)(rowB + n) = oB;
        }
    }
}

// -------------------- fp32 GEMM for K/V projections -----------------------
__global__ __launch_bounds__(256) void gemm_kv(
    const float* __restrict__ cond,
    const float* __restrict__ wk, const float* __restrict__ bk,
    const float* __restrict__ wv, const float* __restrict__ bv)
{
    __shared__ float As[128][17];
    __shared__ float Bs[128][17];
    const float* W    = blockIdx.z ? wv : wk;
    const float* bias = blockIdx.z ? bv : bk;
    float* out        = blockIdx.z ? g_v : g_k;

    int tid = threadIdx.x;
    int ty = tid >> 4, tx = tid & 15;
    int m0 = blockIdx.y * 128, n0 = blockIdx.x * 128;

    float acc[8][8];
#pragma unroll
    for (int i = 0; i < 8; i++)
#pragma unroll
        for (int j = 0; j < 8; j++) acc[i][j] = 0.f;

    for (int ks = 0; ks < CC; ks += 16) {
#pragma unroll
        for (int t = 0; t < 8; t++) {
            int idx = tid + t * 256;
            int r = idx >> 4, c = idx & 15;
            As[r][c] = cond[(size_t)(m0 + r) * CC + ks + c];
            Bs[r][c] = W[(size_t)(n0 + r) * CC + ks + c];
        }
        __syncthreads();
#pragma unroll
        for (int kk = 0; kk < 16; kk++) {
            float a[8], b[8];
#pragma unroll
            for (int i = 0; i < 8; i++) a[i] = As[ty * 8 + i][kk];
#pragma unroll
            for (int j = 0; j < 8; j++) b[j] = Bs[tx + j * 16][kk];
#pragma unroll
            for (int i = 0; i < 8; i++)
#pragma unroll
                for (int j = 0; j < 8; j++)
                    acc[i][j] = fmaf(a[i], b[j], acc[i][j]);
        }
        __syncthreads();
    }

#pragma unroll
    for (int i = 0; i < 8; i++) {
        int m = m0 + ty * 8 + i;
#pragma unroll
        for (int j = 0; j < 8; j++) {
            int n = n0 + tx + j * 16;
            out[(size_t)m * CC + n] = acc[i][j] + bias[n];
        }
    }
}

// -------------------- flash-style cross attention --------------------------
#define ATT_QK_STRIDE 129
#define ATT_S_STRIDE  65
#define ATT_SMEM ((3*64*ATT_QK_STRIDE + 64*ATT_S_STRIDE) * (int)sizeof(float))

__global__ __launch_bounds__(256) void attn_kernel(const float* __restrict__ mask)
{
    extern __shared__ float sm[];
    float* qs  = sm;                          // 64 x 129
    float* ks_ = qs  + 64 * ATT_QK_STRIDE;    // 64 x 129
    float* vs  = ks_ + 64 * ATT_QK_STRIDE;    // 64 x 129
    float* ss  = vs  + 64 * ATT_QK_STRIDE;    // 64 x 65

    int bh = blockIdx.y;
    int b = bh >> 4, h = bh & 15;
    int n0 = blockIdx.x * 64;
    int tid = threadIdx.x;
    int ty = tid >> 4, tx = tid & 15;
    const float inv_sqrt_d = 0.088388347648318447f;   // 1/sqrt(128)

    for (int idx = tid; idx < 64 * 128; idx += 256) {
        int r = idx >> 7, d = idx & 127;
        qs[r * ATT_QK_STRIDE + d] =
            g_q[((size_t)b * NN + n0 + r) * CC + h * DD + d] * inv_sqrt_d;
    }

    float m_i[4], l_i[4], oacc[4][8];
#pragma unroll
    for (int i = 0; i < 4; i++) {
        m_i[i] = -INFINITY;
        l_i[i] = 0.f;
#pragma unroll
        for (int k = 0; k < 8; k++) oacc[i][k] = 0.f;
    }

    for (int c0 = 0; c0 < LL; c0 += 64) {
        __syncthreads();
        for (int idx = tid; idx < 64 * 128; idx += 256) {
            int r = idx >> 7, d = idx & 127;
            size_t g = ((size_t)b * LL + c0 + r) * CC + h * DD + d;
            ks_[r * ATT_QK_STRIDE + d] = g_k[g];
            vs [r * ATT_QK_STRIDE + d] = g_v[g];
        }
        __syncthreads();

        float sacc[4][4];
#pragma unroll
        for (int i = 0; i < 4; i++)
#pragma unroll
            for (int j = 0; j < 4; j++) sacc[i][j] = 0.f;

#pragma unroll 8
        for (int d = 0; d < 128; d++) {
            float a[4], bb[4];
#pragma unroll
            for (int i = 0; i < 4; i++) a[i] = qs[(ty * 4 + i) * ATT_QK_STRIDE + d];
#pragma unroll
            for (int j = 0; j < 4; j++) bb[j] = ks_[(tx + j * 16) * ATT_QK_STRIDE + d];
#pragma unroll
            for (int i = 0; i < 4; i++)
#pragma unroll
                for (int j = 0; j < 4; j++) sacc[i][j] = fmaf(a[i], bb[j], sacc[i][j]);
        }

#pragma unroll
        for (int i = 0; i < 4; i++) {
            int row = n0 + ty * 4 + i;
            float rmax = -INFINITY;
#pragma unroll
            for (int j = 0; j < 4; j++) {
                sacc[i][j] += mask[((size_t)b * NN + row) * LL + c0 + tx + j * 16];
                rmax = fmaxf(rmax, sacc[i][j]);
            }
#pragma unroll
            for (int off = 1; off < 16; off <<= 1)
                rmax = fmaxf(rmax, __shfl_xor_sync(0xffffffffu, rmax, off));

            float nm = fmaxf(m_i[i], rmax);
            float corr = __expf(m_i[i] - nm);
            m_i[i] = nm;
            float ps = 0.f;
#pragma unroll
            for (int j = 0; j < 4; j++) {
                float p = __expf(sacc[i][j] - nm);
                sacc[i][j] = p;
                ps += p;
            }
#pragma unroll
            for (int off = 1; off < 16; off <<= 1)
                ps += __shfl_xor_sync(0xffffffffu, ps, off);
            l_i[i] = l_i[i] * corr + ps;
#pragma unroll
            for (int k = 0; k < 8; k++) oacc[i][k] *= corr;
        }

#pragma unroll
        for (int i = 0; i < 4; i++)
#pragma unroll
            for (int j = 0; j < 4; j++)
                ss[(ty * 4 + i) * ATT_S_STRIDE + tx + j * 16] = sacc[i][j];
        __syncthreads();

#pragma unroll 4
        for (int jj = 0; jj < 64; jj++) {
            float p4[4], v8[8];
#pragma unroll
            for (int i = 0; i < 4; i++) p4[i] = ss[(ty * 4 + i) * ATT_S_STRIDE + jj];
#pragma unroll
            for (int k = 0; k < 8; k++) v8[k] = vs[jj * ATT_QK_STRIDE + tx + k * 16];
#pragma unroll
            for (int i = 0; i < 4; i++)
#pragma unroll
                for (int k = 0; k < 8; k++) oacc[i][k] = fmaf(p4[i], v8[k], oacc[i][k]);
        }
    }

#pragma unroll
    for (int i = 0; i < 4; i++) {
        float inv = 1.f / l_i[i];
        int row = n0 + ty * 4 + i;
#pragma unroll
        for (int k = 0; k < 8; k++)
            g_o[((size_t)b * NN + row) * CC + h * DD + tx + k * 16] = oacc[i][k] * inv;
    }
}

// -------------------- launcher --------------------------------------------
extern "C" void kernel_launch(void* const* d_in, const int* in_sizes, int n_in,
                              void* d_out, int out_size) {
    const float* x    = (const float*)d_in[0];
    const float* cond = (const float*)d_in[1];
    const float* mask = (const float*)d_in[2];
    const float* wq   = (const float*)d_in[3];
    const float* bq   = (const float*)d_in[4];
    const float* wk   = (const float*)d_in[5];
    const float* bk   = (const float*)d_in[6];
    const float* wv   = (const float*)d_in[7];
    const float* bv   = (const float*)d_in[8];
    const float* wo   = (const float*)d_in[9];
    const float* bo   = (const float*)d_in[10];
    float* out = (float*)d_out;

    void *p_qwq, *p_swq, *p_qwo, *p_swo, *p_qx, *p_sx, *p_q, *p_o, *p_qo, *p_so;
    cudaGetSymbolAddress(&p_qwq, g_qwq);
    cudaGetSymbolAddress(&p_swq, g_swq);
    cudaGetSymbolAddress(&p_qwo, g_qwo);
    cudaGetSymbolAddress(&p_swo, g_swo);
    cudaGetSymbolAddress(&p_qx,  g_qx);
    cudaGetSymbolAddress(&p_sx,  g_sx);
    cudaGetSymbolAddress(&p_q,   g_q);
    cudaGetSymbolAddress(&p_o,   g_o);
    cudaGetSymbolAddress(&p_qo,  g_qo);
    cudaGetSymbolAddress(&p_so,  g_so);

    cudaFuncSetAttribute(gemm_tc,
                         cudaFuncAttributeMaxDynamicSharedMemorySize, GEMM_SMEM);
    cudaFuncSetAttribute(attn_kernel,
                         cudaFuncAttributeMaxDynamicSharedMemorySize, ATT_SMEM);

    // 1. quantize weights (wq, wo) and activations (x) -> bf16-exact ints
    quant_rows<<<CC, 256>>>(wq, (__nv_bfloat16*)p_qwq, (float*)p_swq, CC);
    quant_rows<<<CC, 256>>>(wo, (__nv_bfloat16*)p_qwo, (float*)p_swo, CC);
    quant_rows<<<MTOK, 256>>>(x, (__nv_bfloat16*)p_qx, (float*)p_sx, CC);

    // 2. Q projection (W8A8 via mma.sync bf16, int32-exact)
    gemm_tc<<<dim3(CC / 128, MTOK / 128), 256, GEMM_SMEM>>>(
        (const __nv_bfloat16*)p_qx, (const __nv_bfloat16*)p_qwq,
        (const float*)p_sx, (const float*)p_swq, bq, (float*)p_q);

    // 3. K/V projections (fp32), fused across z
    gemm_kv<<<dim3(CC / 128, MKV / 128, 2), 256>>>(cond, wk, bk, wv, bv);

    // 4. attention
    attn_kernel<<<dim3(NN / 64, BB * HH), 256, ATT_SMEM>>>(mask);

    // 5. quantize attention output, O projection (W8A8) into d_out
    quant_rows<<<MTOK, 256>>>((const float*)p_o, (__nv_bfloat16*)p_qo, (float*)p_so, CC);
    gemm_tc<<<dim3(CC / 128, MTOK / 128), 256, GEMM_SMEM>>>(
        (const __nv_bfloat16*)p_qo, (const __nv_bfloat16*)p_qwo,
        (const float*)p_so, (const float*)p_swo, bo, out);
}